// round 1
// baseline (speedup 1.0000x reference)
#include <cuda_runtime.h>
#include <cstdint>

typedef unsigned long long ull;

// Problem constants
#define BB   4
#define CC   128
#define HH   96
#define WW   96
#define OC   18          // G*K*K*2
#define HWP  (HH*WW)     // 9216
#define NPIX (BB*HWP)    // 36864
#define NCHUNK 4         // channel split for conv grid fill

// ---------------- scratch (static device arrays; no allocation) ----------------
__device__ float  g_rotp[NCHUNK * BB * OC * HWP];   // partial conv sums [chunk][b][o][h][w]
__device__ float4 g_coef[9 * NPIX];                  // bilinear coefs, planar [tap][pix]
__device__ unsigned int g_idx[9 * NPIX];             // packed 4x byte gather indices

// ---------------- f32x2 helpers ----------------
__device__ __forceinline__ ull packf2(float a, float b) {
    ull r; asm("mov.b64 %0, {%1, %2};" : "=l"(r) : "f"(a), "f"(b)); return r;
}
__device__ __forceinline__ ull dupf2(float a) {
    ull r; asm("mov.b64 %0, {%1, %1};" : "=l"(r) : "f"(a)); return r;
}
__device__ __forceinline__ void unpackf2(ull v, float& a, float& b) {
    asm("mov.b64 {%0, %1}, %2;" : "=f"(a), "=f"(b) : "l"(v));
}
__device__ __forceinline__ void fma2(ull& d, ull a, ull b) {
    asm("fma.rn.f32x2 %0, %1, %2, %0;" : "+l"(d) : "l"(a), "l"(b));
}
__device__ __forceinline__ ull mul2(ull a, ull b) {
    ull r; asm("mul.rn.f32x2 %0, %1, %2;" : "=l"(r) : "l"(a), "l"(b)); return r;
}

// ============================================================================
// Kernel 1: rotation conv (18 out-ch, 128 in-ch, 3x3, pad 1), fp32 via f32x2.
// Block = 192 threads: col(32) x ogroup(3, 6 outputs each) x rowgroup(2).
// Tile = 16 pixel-rows x 32 cols. Channels split into 4 chunks of 32 (partials).
// Vertical f32x2 pairing: thread accumulates pixel rows (r, r+4) packed.
// Smem holds pre-paired x: Psm[j] = { x[h0-1+j], x[h0+3+j] }.
// ============================================================================
__global__ __launch_bounds__(192, 2)
void conv_kernel(const float* __restrict__ x, const float* __restrict__ rw)
{
    const int tid = threadIdx.x;
    const int col = tid & 31;          // 0..31
    const int og  = (tid >> 5) % 3;    // 0..2  -> outputs og*6 .. og*6+5
    const int rg  = tid / 96;          // 0..1  -> pixel rows h0+8rg .. +7

    const int w0 = blockIdx.x * 32;
    const int h0 = blockIdx.y * 16;
    const int b     = blockIdx.z >> 2;
    const int chunk = blockIdx.z & 3;
    const int cbase = chunk * 32;

    __shared__ float2 Psm[14][34];
    __shared__ float  ws[OC * 9];

    ull acc[6][4];
    #pragma unroll
    for (int o9 = 0; o9 < 6; o9++)
        #pragma unroll
        for (int k = 0; k < 4; k++) acc[o9][k] = 0ull;

    const float* xb = x + (size_t)b * CC * HWP;

    for (int ci = 0; ci < 32; ci++) {
        const int c = cbase + ci;
        __syncthreads();
        // stage this channel's 18x9 weights
        for (int i = tid; i < OC * 9; i += 192) {
            int o = i / 9, t = i - o * 9;
            ws[i] = rw[(o * CC + c) * 9 + t];
        }
        // stage pre-paired x tile: rows h0-1 .. h0+16 (18), cols w0-1 .. w0+32 (34)
        const float* xc = xb + (size_t)c * HWP;
        for (int i = tid; i < 18 * 34; i += 192) {
            int rh = i / 34, ccx = i - rh * 34;
            int gr = h0 - 1 + rh, gc = w0 - 1 + ccx;
            float v = 0.0f;
            if ((unsigned)gr < (unsigned)HH && (unsigned)gc < (unsigned)WW)
                v = xc[gr * WW + gc];
            if (rh <= 13) Psm[rh][ccx].x = v;     // row (h0-1+rh)
            if (rh >= 4)  Psm[rh - 4][ccx].y = v; // row (h0+3+(rh-4)) = same row, +4 partner
        }
        __syncthreads();

        #pragma unroll
        for (int di = 0; di < 3; di++) {
            // pv[k][dj] = { x[r0+k+di-1][w+dj-1], x[r0+k+4+di-1][w+dj-1] }
            ull pv[4][3];
            #pragma unroll
            for (int k = 0; k < 4; k++)
                #pragma unroll
                for (int dj = 0; dj < 3; dj++)
                    pv[k][dj] = *(const ull*)&Psm[8 * rg + di + k][col + dj];

            #pragma unroll
            for (int o9 = 0; o9 < 6; o9++) {
                const int o = og * 6 + o9;
                #pragma unroll
                for (int dj = 0; dj < 3; dj++) {
                    ull w2 = dupf2(ws[o * 9 + di * 3 + dj]);
                    #pragma unroll
                    for (int k = 0; k < 4; k++)
                        fma2(acc[o9][k], w2, pv[k][dj]);
                }
            }
        }
    }

    // write partials
    float* rp = g_rotp + (size_t)(chunk * BB + b) * OC * HWP;
    #pragma unroll
    for (int o9 = 0; o9 < 6; o9++) {
        const int o = og * 6 + o9;
        #pragma unroll
        for (int k = 0; k < 4; k++) {
            float lo, hi; unpackf2(acc[o9][k], lo, hi);
            int r0 = h0 + 8 * rg + k;
            rp[o * HWP + r0 * WW + w0 + col]       = lo;
            rp[o * HWP + (r0 + 4) * WW + w0 + col] = hi;
        }
    }
}

// ============================================================================
// Kernel 2: per (pixel, tap) coordinate -> bilinear coefs + packed indices.
// ============================================================================
__global__ void coef_kernel(const float* __restrict__ rb)
{
    const int pix = blockIdx.x * 256 + threadIdx.x;
    if (pix >= NPIX) return;
    const int b = pix / HWP;
    const int rem = pix - b * HWP;

    float s[OC];
    #pragma unroll
    for (int o = 0; o < OC; o++) {
        float v = rb[o];
        #pragma unroll
        for (int ch = 0; ch < NCHUNK; ch++)
            v += g_rotp[((size_t)(ch * BB + b) * OC + o) * HWP + rem];
        s[o] = v;
    }

    #pragma unroll
    for (int t = 0; t < 9; t++) {
        const int i = t / 3, j = t % 3;
        // fc_bias start = (KS-(K-1)-1)/2 = 0.5
        float chv = s[2 * t]     + 0.5f + (float)i;
        float cwv = s[2 * t + 1] + 0.5f + (float)j;
        chv = fminf(fmaxf(chv, 0.0f), 3.0f);
        cwv = fminf(fmaxf(cwv, 0.0f), 3.0f);
        float h0f = floorf(chv), w0f = floorf(cwv);
        float lh = chv - h0f, lw = cwv - w0f;
        int h0i = (int)h0f, w0i = (int)w0f;
        int h1i = min(h0i + 1, 3), w1i = min(w0i + 1, 3);
        float4 cf;
        cf.x = (1.0f - lh) * (1.0f - lw);
        cf.y = (1.0f - lh) * lw;
        cf.z = lh * (1.0f - lw);
        cf.w = lh * lw;
        g_coef[t * NPIX + pix] = cf;
        g_idx[t * NPIX + pix] =
            (unsigned)(h0i * 4 + w0i)        |
            ((unsigned)(h0i * 4 + w1i) << 8) |
            ((unsigned)(h1i * 4 + w0i) << 16)|
            ((unsigned)(h1i * 4 + w1i) << 24);
    }
}

// ============================================================================
// Kernel 3: deform gather + accumulate. Block = 64 threads, one 32-pixel row
// segment; thread cp handles channels cp and cp+64 (f32x2 paired).
// Weight table in smem transposed+channel-paired: wt2[slot][cp] = (w[cp][slot], w[cp+64][slot])
// -> every gather is one conflict-free coalesced LDS.64 serving 2 channels.
// ============================================================================
__global__ __launch_bounds__(64)
void deform_kernel(const float* __restrict__ x, const float* __restrict__ wt,
                   float* __restrict__ out)
{
    __shared__ float2 wt2[16][64];
    __shared__ float4 cfs[9][32];
    __shared__ unsigned int ids[9][32];

    const int cp = threadIdx.x;         // 0..63
    const int w0 = blockIdx.x * 32;
    const int h  = blockIdx.y;
    const int b  = blockIdx.z;

    #pragma unroll
    for (int s = 0; s < 16; s++)
        wt2[s][cp] = make_float2(wt[cp * 16 + s], wt[(cp + 64) * 16 + s]);

    const int pixbase = b * HWP + h * WW + w0;
    for (int i = cp; i < 9 * 32; i += 64) {
        int t = i >> 5, p = i & 31;
        cfs[t][p] = g_coef[t * NPIX + pixbase + p];
        ids[t][p] = g_idx[t * NPIX + pixbase + p];
    }
    __syncthreads();

    const float* x0 = x + (size_t)(b * CC + cp) * HWP;
    const float* x1 = x0 + (size_t)64 * HWP;
    const bool rok0 = (h >= 1), rok2 = (h <= HH - 2);

    // sliding 3x3 window of channel-paired x values
    ull xv[3][3];
    {
        // columns w0-1 and w0
        #pragma unroll
        for (int dj = 0; dj < 2; dj++) {
            int gc = w0 - 1 + dj;
            bool cok = (unsigned)gc < (unsigned)WW;
            #pragma unroll
            for (int di = 0; di < 3; di++) {
                bool ok = cok && ((di == 0) ? rok0 : (di == 2) ? rok2 : true);
                int gr = h + di - 1;
                float a = 0.0f, bv = 0.0f;
                if (ok) { a = x0[gr * WW + gc]; bv = x1[gr * WW + gc]; }
                xv[di][dj] = packf2(a, bv);
            }
        }
    }

    for (int p = 0; p < 32; p++) {
        // load new right column (w0+p+1)
        {
            int gc = w0 + p + 1;
            bool cok = gc < WW;
            #pragma unroll
            for (int di = 0; di < 3; di++) {
                bool ok = cok && ((di == 0) ? rok0 : (di == 2) ? rok2 : true);
                int gr = h + di - 1;
                float a = 0.0f, bv = 0.0f;
                if (ok) { a = x0[gr * WW + gc]; bv = x1[gr * WW + gc]; }
                xv[di][2] = packf2(a, bv);
            }
        }

        ull acc = 0ull;
        #pragma unroll
        for (int t = 0; t < 9; t++) {
            const float4 cf = cfs[t][p];        // warp-uniform broadcast
            const unsigned ox = ids[t][p];
            const unsigned i0 =  ox        & 0xffu;
            const unsigned i1 = (ox >> 8)  & 0xffu;
            const unsigned i2 = (ox >> 16) & 0xffu;
            const unsigned i3 =  ox >> 24;
            ull g00 = *(const ull*)&wt2[i0][cp];
            ull g01 = *(const ull*)&wt2[i1][cp];
            ull g10 = *(const ull*)&wt2[i2][cp];
            ull g11 = *(const ull*)&wt2[i3][cp];
            ull wsamp = mul2(dupf2(cf.x), g00);
            fma2(wsamp, dupf2(cf.y), g01);
            fma2(wsamp, dupf2(cf.z), g10);
            fma2(wsamp, dupf2(cf.w), g11);
            fma2(acc, wsamp, xv[t / 3][t % 3]);
        }

        float lo, hi; unpackf2(acc, lo, hi);
        const int off = h * WW + w0 + p;
        out[(size_t)(b * CC + cp) * HWP + off]        = lo;
        out[(size_t)(b * CC + cp + 64) * HWP + off]   = hi;

        // shift window
        #pragma unroll
        for (int di = 0; di < 3; di++) { xv[di][0] = xv[di][1]; xv[di][1] = xv[di][2]; }
    }
}

// ============================================================================
extern "C" void kernel_launch(void* const* d_in, const int* in_sizes, int n_in,
                              void* d_out, int out_size)
{
    const float* x  = (const float*)d_in[0];   // [4,128,96,96]
    const float* rw = (const float*)d_in[1];   // [18,128,3,3]
    const float* rb = (const float*)d_in[2];   // [18]
    const float* wt = (const float*)d_in[3];   // [128,4,4]
    float* out = (float*)d_out;                // [4,128,96,96]

    conv_kernel<<<dim3(3, 6, BB * NCHUNK), 192>>>(x, rw);
    coef_kernel<<<(NPIX + 255) / 256, 256>>>(rb);
    deform_kernel<<<dim3(3, HH, BB), 64>>>(x, wt, out);
}

// round 2
// speedup vs baseline: 1.7696x; 1.7696x over previous
#include <cuda_runtime.h>
#include <cstdint>

typedef unsigned long long ull;
typedef unsigned int uint;

// Problem constants
#define BB   4
#define CC   128
#define HH   96
#define WW   96
#define OC   18          // G*K*K*2
#define HWP  (HH*WW)     // 9216
#define NPIX (BB*HWP)    // 36864
#define CHUNKS 2         // channel split for conv
#define CPC  (CC/CHUNKS) // 64 channels per chunk

// ---------------- scratch (static device arrays; no allocation) ----------------
__device__ float  g_rotp[CHUNKS * BB * OC * HWP];     // partial conv sums [chunk][b][o][h][w]
__device__ float2 g_xt[(size_t)BB * HWP * 64];        // NHWC channel-paired: [b][h][w][cp]=(x[cp],x[cp+64])

// ---------------- f32x2 helpers ----------------
__device__ __forceinline__ ull packf2(float a, float b) {
    ull r; asm("mov.b64 %0, {%1, %2};" : "=l"(r) : "f"(a), "f"(b)); return r;
}
__device__ __forceinline__ ull dupf2(float a) {
    ull r; asm("mov.b64 %0, {%1, %1};" : "=l"(r) : "f"(a)); return r;
}
__device__ __forceinline__ void unpackf2(ull v, float& a, float& b) {
    asm("mov.b64 {%0, %1}, %2;" : "=f"(a), "=f"(b) : "l"(v));
}
__device__ __forceinline__ void fma2(ull& d, ull a, ull b) {
    asm("fma.rn.f32x2 %0, %1, %2, %0;" : "+l"(d) : "l"(a), "l"(b));
}
__device__ __forceinline__ ull mul2(ull a, ull b) {
    ull r; asm("mul.rn.f32x2 %0, %1, %2;" : "=l"(r) : "l"(a), "l"(b)); return r;
}

// ============================================================================
// Kernel 1: rotation conv (18 out-ch, 128 in-ch, 3x3, pad 1), fp32 via f32x2.
// Block = 288 threads: col(32) x og(9, 2 outputs each).
// Tile = 8 pixel-rows x 32 cols (thread holds 4 vertical f32x2 row-pairs).
// Channels split into 2 chunks of 64 (partial-sum buffers, no atomics).
// Double-buffered smem, register prefetch, ONE __syncthreads per channel.
// ============================================================================
__global__ __launch_bounds__(288, 2)
void conv_kernel(const float* __restrict__ x, const float* __restrict__ rw)
{
    const int tid = threadIdx.x;
    const int col = tid & 31;          // 0..31
    const int og  = tid >> 5;          // 0..8  -> outputs 2og, 2og+1

    const int w0 = blockIdx.x * 32;
    const int h0 = blockIdx.y * 8;
    const int b     = blockIdx.z >> 1;
    const int chunk = blockIdx.z & 1;
    const int cbase = chunk * CPC;

    // Ps[buf][j][cc] = { x[h0-1+j][...], x[h0+3+j][...] }  (rows h0-1..h0+8 paired)
    __shared__ float2 Ps[2][6][34];
    __shared__ float  ws[2][OC * 9];

    ull acc[2][4];
    #pragma unroll
    for (int o2 = 0; o2 < 2; o2++)
        #pragma unroll
        for (int k = 0; k < 4; k++) acc[o2][k] = 0ull;

    // ---- prefetch-slot decode (items: 0..339 = x tile (10 rows x 34 cols), 340..501 = weights) ----
    // Slot A: id = tid (always an x item since 288 <= 340... actually 288<340 so yes)
    const int rhA = tid / 34, ccA = tid - rhA * 34;
    const int grA = h0 - 1 + rhA, gcA = w0 - 1 + ccA;
    const bool inbA = ((unsigned)grA < (unsigned)HH) && ((unsigned)gcA < (unsigned)WW);
    const float* gpA = x + ((size_t)(b * CC + cbase)) * HWP + (inbA ? (grA * WW + gcA) : 0);

    // Slot B: id = tid + 288
    const int idB = tid + 288;
    const bool isxB = (idB < 340);                 // tid < 52
    const bool iswB = (idB >= 340) && (idB < 502); // tid in [52, 214)
    int rhB = 0, ccB = 0, wiB = 0; bool inbB = false;
    const float* gpB = x;
    if (isxB) {
        rhB = idB / 34; ccB = idB - rhB * 34;
        int gr = h0 - 1 + rhB, gc = w0 - 1 + ccB;
        inbB = ((unsigned)gr < (unsigned)HH) && ((unsigned)gc < (unsigned)WW);
        gpB = x + ((size_t)(b * CC + cbase)) * HWP + (inbB ? (gr * WW + gc) : 0);
    } else if (iswB) {
        wiB = idB - 340;
        int o = wiB / 9, t9 = wiB - o * 9;
        gpB = rw + ((size_t)o * CC + cbase) * 9 + t9;
    }

    // ---- prologue: channel cbase -> buffer 0 ----
    {
        float a = inbA ? gpA[0] : 0.0f;
        float bv = 0.0f;
        if (isxB) bv = inbB ? gpB[0] : 0.0f;
        else if (iswB) bv = gpB[0];

        if (rhA <= 5) Ps[0][rhA][ccA].x = a;
        if (rhA >= 4) Ps[0][rhA - 4][ccA].y = a;
        if (isxB) {
            if (rhB <= 5) Ps[0][rhB][ccB].x = bv;
            if (rhB >= 4) Ps[0][rhB - 4][ccB].y = bv;
        } else if (iswB) ws[0][wiB] = bv;
    }
    __syncthreads();

    for (int ci = 0; ci < CPC; ci++) {
        const int buf = ci & 1;
        const bool more = (ci + 1 < CPC);
        float nA = 0.0f, nB = 0.0f;
        if (more) {
            gpA += HWP;
            nA = inbA ? gpA[0] : 0.0f;
            if (isxB)      { gpB += HWP; nB = inbB ? gpB[0] : 0.0f; }
            else if (iswB) { gpB += 9;   nB = gpB[0]; }
        }

        // ---- compute on buffer `buf` ----
        const float* wsp = &ws[buf][2 * og * 9];
        #pragma unroll
        for (int di = 0; di < 3; di++) {
            ull w2[6];
            #pragma unroll
            for (int o2 = 0; o2 < 2; o2++)
                #pragma unroll
                for (int dj = 0; dj < 3; dj++)
                    w2[o2 * 3 + dj] = dupf2(wsp[o2 * 9 + di * 3 + dj]);
            #pragma unroll
            for (int k = 0; k < 4; k++) {
                ull pv[3];
                #pragma unroll
                for (int dj = 0; dj < 3; dj++)
                    pv[dj] = *(const ull*)&Ps[buf][k + di][col + dj];
                #pragma unroll
                for (int o2 = 0; o2 < 2; o2++)
                    #pragma unroll
                    for (int dj = 0; dj < 3; dj++)
                        fma2(acc[o2][k], w2[o2 * 3 + dj], pv[dj]);
            }
        }

        // ---- store prefetched channel into the other buffer ----
        // Safe: buf^1 was last READ in iteration ci-1, which ended with a sync.
        if (more) {
            if (rhA <= 5) Ps[buf ^ 1][rhA][ccA].x = nA;
            if (rhA >= 4) Ps[buf ^ 1][rhA - 4][ccA].y = nA;
            if (isxB) {
                if (rhB <= 5) Ps[buf ^ 1][rhB][ccB].x = nB;
                if (rhB >= 4) Ps[buf ^ 1][rhB - 4][ccB].y = nB;
            } else if (iswB) ws[buf ^ 1][wiB] = nB;
        }
        __syncthreads();
    }

    // ---- write partials ----
    float* rp = g_rotp + (size_t)(chunk * BB + b) * OC * HWP;
    #pragma unroll
    for (int o2 = 0; o2 < 2; o2++) {
        const int o = 2 * og + o2;
        #pragma unroll
        for (int k = 0; k < 4; k++) {
            float lo, hi; unpackf2(acc[o2][k], lo, hi);
            rp[(size_t)o * HWP + (h0 + k) * WW + w0 + col]     = lo;
            rp[(size_t)o * HWP + (h0 + 4 + k) * WW + w0 + col] = hi;
        }
    }
}

// ============================================================================
// Kernel 2: transpose x NCHW -> NHWC channel-paired float2 (for deform).
// Makes deform's x loads fully coalesced (warp lanes = channels).
// ============================================================================
__global__ __launch_bounds__(256)
void transpose_kernel(const float* __restrict__ x)
{
    __shared__ float2 t[64][33];
    const int tid = threadIdx.x;
    const int tx = tid & 31, ty = tid >> 5;       // ty 0..7
    const int w0 = blockIdx.x * 32, h = blockIdx.y, b = blockIdx.z;

    const float* xb = x + ((size_t)b * CC) * HWP + h * WW + w0;
    #pragma unroll
    for (int k = 0; k < 8; k++) {
        int c = ty + 8 * k;                       // 0..63
        float v0 = xb[(size_t)c * HWP + tx];
        float v1 = xb[(size_t)(c + 64) * HWP + tx];
        t[c][tx] = make_float2(v0, v1);
    }
    __syncthreads();

    float2* ob = g_xt + ((size_t)(b * HH + h) * WW + w0) * 64;
    #pragma unroll
    for (int k = 0; k < 8; k++) {
        int cp = tx + 32 * (k & 1);
        int wl = ty + 8 * (k >> 1);
        ob[(size_t)wl * 64 + cp] = t[cp][wl];
    }
}

// ============================================================================
// Kernel 3: fused coef + deform gather.
// Block = 256 threads: cp(64) x pg(4 rows). Tile = 4 rows x 12 pixels.
// Prologue computes bilinear coefs + packed gather indices for the block's
// 48 pixels directly from g_rotp partials (no separate coef kernel).
// Thread cp handles channels cp and cp+64 (f32x2 paired).
// Weight table smem transposed+channel-paired -> all gathers are
// conflict-free coalesced LDS.64 serving 2 channels.
// x reads from NHWC float2 (coalesced), 3x3 sliding window per thread.
// ============================================================================
__global__ __launch_bounds__(256)
void deform_kernel(const float* __restrict__ wt, const float* __restrict__ rb,
                   float* __restrict__ out)
{
    __shared__ float2 wt2[16][64];
    __shared__ float4 cfs[4][9][12];
    __shared__ uint   ids[4][9][12];

    const int tid = threadIdx.x;
    const int cp = tid & 63;            // channel pair lane
    const int pg = tid >> 6;            // row within block tile (0..3)
    const int w0 = blockIdx.x * 12;
    const int hb = blockIdx.y * 4;
    const int b  = blockIdx.z;
    const int h  = hb + pg;

    // stage channel-paired weight table
    for (int i = tid; i < 16 * 64; i += 256) {
        int s = i >> 6, c = i & 63;
        wt2[s][c] = make_float2(wt[c * 16 + s], wt[(c + 64) * 16 + s]);
    }

    // fused coef: items (r 0..3, t 0..8, p 0..11) = 432
    for (int i = tid; i < 432; i += 256) {
        int r = i / 108; int rem = i - r * 108;
        int t = rem / 12; int p = rem - t * 12;
        int off = (hb + r) * WW + w0 + p;
        const float* rp0 = g_rotp + ((size_t)(0 * BB + b) * OC) * HWP + off;
        const float* rp1 = g_rotp + ((size_t)(1 * BB + b) * OC) * HWP + off;
        int o0 = 2 * t, o1 = 2 * t + 1;
        // fc_bias start = (KS-(K-1)-1)/2 = 0.5
        float chv = rb[o0] + rp0[(size_t)o0 * HWP] + rp1[(size_t)o0 * HWP] + 0.5f + (float)(t / 3);
        float cwv = rb[o1] + rp0[(size_t)o1 * HWP] + rp1[(size_t)o1 * HWP] + 0.5f + (float)(t % 3);
        chv = fminf(fmaxf(chv, 0.0f), 3.0f);
        cwv = fminf(fmaxf(cwv, 0.0f), 3.0f);
        float h0f = floorf(chv), w0f = floorf(cwv);
        float lh = chv - h0f, lw = cwv - w0f;
        int h0i = (int)h0f, w0i = (int)w0f;
        int h1i = min(h0i + 1, 3), w1i = min(w0i + 1, 3);
        float4 cf;
        cf.x = (1.0f - lh) * (1.0f - lw);
        cf.y = (1.0f - lh) * lw;
        cf.z = lh * (1.0f - lw);
        cf.w = lh * lw;
        cfs[r][t][p] = cf;
        ids[r][t][p] = (uint)(h0i * 4 + w0i)
                     | ((uint)(h0i * 4 + w1i) << 8)
                     | ((uint)(h1i * 4 + w0i) << 16)
                     | ((uint)(h1i * 4 + w1i) << 24);
    }
    __syncthreads();

    const float2* xt = g_xt + (size_t)b * HWP * 64 + cp;
    const bool rok0 = (h >= 1), rok2 = (h <= HH - 2);

    // sliding 3x3 window of channel-paired x values
    ull xv[3][3];
    #pragma unroll
    for (int dj = 0; dj < 2; dj++) {
        int gc = w0 - 1 + dj;
        bool cok = (unsigned)gc < (unsigned)WW;
        #pragma unroll
        for (int di = 0; di < 3; di++) {
            bool ok = cok && ((di == 0) ? rok0 : (di == 2) ? rok2 : true);
            ull v = 0ull;
            if (ok) v = *(const ull*)(xt + ((size_t)(h + di - 1) * WW + gc) * 64);
            xv[di][dj] = v;
        }
    }

    for (int p = 0; p < 12; p++) {
        { // load new right column
            int gc = w0 + p + 1;
            bool cok = gc < WW;
            #pragma unroll
            for (int di = 0; di < 3; di++) {
                bool ok = cok && ((di == 0) ? rok0 : (di == 2) ? rok2 : true);
                ull v = 0ull;
                if (ok) v = *(const ull*)(xt + ((size_t)(h + di - 1) * WW + gc) * 64);
                xv[di][2] = v;
            }
        }

        ull acc = 0ull;
        #pragma unroll
        for (int t = 0; t < 9; t++) {
            const float4 cf = cfs[pg][t][p];    // warp-uniform broadcast
            const uint ox = ids[pg][t][p];
            ull g00 = *(const ull*)&wt2[ ox        & 15u][cp];
            ull g01 = *(const ull*)&wt2[(ox >> 8)  & 15u][cp];
            ull g10 = *(const ull*)&wt2[(ox >> 16) & 15u][cp];
            ull g11 = *(const ull*)&wt2[(ox >> 24) & 15u][cp];
            ull wsamp = mul2(dupf2(cf.x), g00);
            fma2(wsamp, dupf2(cf.y), g01);
            fma2(wsamp, dupf2(cf.z), g10);
            fma2(wsamp, dupf2(cf.w), g11);
            fma2(acc, wsamp, xv[t / 3][t % 3]);
        }

        float lo, hi; unpackf2(acc, lo, hi);
        const int off = h * WW + w0 + p;
        out[(size_t)(b * CC + cp) * HWP + off]      = lo;
        out[(size_t)(b * CC + cp + 64) * HWP + off] = hi;

        #pragma unroll
        for (int di = 0; di < 3; di++) { xv[di][0] = xv[di][1]; xv[di][1] = xv[di][2]; }
    }
}

// ============================================================================
extern "C" void kernel_launch(void* const* d_in, const int* in_sizes, int n_in,
                              void* d_out, int out_size)
{
    const float* x  = (const float*)d_in[0];   // [4,128,96,96]
    const float* rw = (const float*)d_in[1];   // [18,128,3,3]
    const float* rb = (const float*)d_in[2];   // [18]
    const float* wt = (const float*)d_in[3];   // [128,4,4]
    float* out = (float*)d_out;                // [4,128,96,96]

    conv_kernel<<<dim3(3, 12, BB * CHUNKS), 288>>>(x, rw);
    transpose_kernel<<<dim3(3, HH, BB), 256>>>(x);
    deform_kernel<<<dim3(8, 24, BB), 256>>>(wt, rb, out);
}

// round 3
// speedup vs baseline: 2.0405x; 1.1531x over previous
#include <cuda_runtime.h>
#include <cstdint>

typedef unsigned long long ull;
typedef unsigned int uint;

// Problem constants
#define BB   4
#define CC   128
#define HH   96
#define WW   96
#define OC   18          // G*K*K*2
#define HWP  (HH*WW)     // 9216
#define CHUNKS 4         // channel split for conv
#define CPC  (CC/CHUNKS) // 32 channels per chunk

// ---------------- scratch (static device arrays; no allocation) ----------------
__device__ float  g_rotp[CHUNKS * BB * OC * HWP];     // partial conv sums [chunk][b][o][h][w]
__device__ float2 g_xt[(size_t)BB * HWP * 64];        // NHWC channel-paired: [b][h][w][cp]=(x[cp],x[cp+64])

// ---------------- f32x2 helpers ----------------
__device__ __forceinline__ ull dupf2(float a) {
    ull r; asm("mov.b64 %0, {%1, %1};" : "=l"(r) : "f"(a)); return r;
}
__device__ __forceinline__ void unpackf2(ull v, float& a, float& b) {
    asm("mov.b64 {%0, %1}, %2;" : "=f"(a), "=f"(b) : "l"(v));
}
__device__ __forceinline__ void fma2(ull& d, ull a, ull b) {
    asm("fma.rn.f32x2 %0, %1, %2, %0;" : "+l"(d) : "l"(a), "l"(b));
}
__device__ __forceinline__ ull mul2(ull a, ull b) {
    ull r; asm("mul.rn.f32x2 %0, %1, %2;" : "=l"(r) : "l"(a), "l"(b)); return r;
}
__device__ __forceinline__ ull add2(ull a, ull b) {
    ull r; asm("add.rn.f32x2 %0, %1, %2;" : "=l"(r) : "l"(a), "l"(b)); return r;
}

// ============================================================================
// Kernel 1: rotation conv (18 out-ch, 128 in-ch, 3x3, pad 1), fp32 via f32x2.
// Block = 288 threads: col(32) x og(9, 2 outputs each).
// Tile = 8 pixel-rows x 32 cols (thread holds 4 vertical f32x2 row-pairs).
// Channels split into 4 chunks of 32 (partial-sum buffers, no atomics).
// Sliding-row register window: each paired row loaded ONCE (18 LDS.64/channel);
// weights pre-duplicated as float2 in smem (18 LDS.64/channel, no movs).
// Double-buffered smem, register prefetch, ONE __syncthreads per channel.
// ============================================================================
__global__ __launch_bounds__(288, 2)
void conv_kernel(const float* __restrict__ x, const float* __restrict__ rw)
{
    const int tid = threadIdx.x;
    const int col = tid & 31;          // 0..31
    const int og  = tid >> 5;          // 0..8  -> outputs 2og, 2og+1

    const int w0 = blockIdx.x * 32;
    const int h0 = blockIdx.y * 8;
    const int b     = blockIdx.z >> 2;
    const int chunk = blockIdx.z & 3;
    const int cbase = chunk * CPC;

    // Ps[buf][j][cc] = { x[h0-1+j][..], x[h0+3+j][..] }  (rows h0-1..h0+8 paired)
    __shared__ float2 Ps[2][6][34];
    __shared__ float2 ws2[2][OC * 9];   // pre-duplicated weights {w,w}

    ull acc[2][4];
    #pragma unroll
    for (int o2 = 0; o2 < 2; o2++)
        #pragma unroll
        for (int k = 0; k < 4; k++) acc[o2][k] = 0ull;

    // ---- prefetch-slot decode (items: 0..339 = x tile (10 rows x 34 cols), 340..501 = weights) ----
    const int rhA = tid / 34, ccA = tid - rhA * 34;
    const int grA = h0 - 1 + rhA, gcA = w0 - 1 + ccA;
    const bool inbA = ((unsigned)grA < (unsigned)HH) && ((unsigned)gcA < (unsigned)WW);
    const float* gpA = x + ((size_t)(b * CC + cbase)) * HWP + (inbA ? (grA * WW + gcA) : 0);

    const int idB = tid + 288;
    const bool isxB = (idB < 340);                 // tid < 52
    const bool iswB = (idB >= 340) && (idB < 502); // tid in [52, 214)
    int rhB = 0, ccB = 0, wiB = 0; bool inbB = false;
    const float* gpB = x;
    if (isxB) {
        rhB = idB / 34; ccB = idB - rhB * 34;
        int gr = h0 - 1 + rhB, gc = w0 - 1 + ccB;
        inbB = ((unsigned)gr < (unsigned)HH) && ((unsigned)gc < (unsigned)WW);
        gpB = x + ((size_t)(b * CC + cbase)) * HWP + (inbB ? (gr * WW + gc) : 0);
    } else if (iswB) {
        wiB = idB - 340;
        int o = wiB / 9, t9 = wiB - o * 9;
        gpB = rw + ((size_t)o * CC + cbase) * 9 + t9;
    }

    // ---- prologue: channel cbase -> buffer 0 ----
    {
        float a = inbA ? gpA[0] : 0.0f;
        float bv = 0.0f;
        if (isxB) bv = inbB ? gpB[0] : 0.0f;
        else if (iswB) bv = gpB[0];

        if (rhA <= 5) Ps[0][rhA][ccA].x = a;
        if (rhA >= 4) Ps[0][rhA - 4][ccA].y = a;
        if (isxB) {
            if (rhB <= 5) Ps[0][rhB][ccB].x = bv;
            if (rhB >= 4) Ps[0][rhB - 4][ccB].y = bv;
        } else if (iswB) ws2[0][wiB] = make_float2(bv, bv);
    }
    __syncthreads();

    for (int ci = 0; ci < CPC; ci++) {
        const int buf = ci & 1;
        const bool more = (ci + 1 < CPC);
        float nA = 0.0f, nB = 0.0f;
        if (more) {
            gpA += HWP;
            nA = inbA ? gpA[0] : 0.0f;
            if (isxB)      { gpB += HWP; nB = inbB ? gpB[0] : 0.0f; }
            else if (iswB) { gpB += 9;   nB = gpB[0]; }
        }

        // ---- compute on buffer `buf` ----
        const float2* wp = &ws2[buf][2 * og * 9];
        ull pv[4][3];
        #pragma unroll
        for (int j = 0; j < 4; j++)
            #pragma unroll
            for (int dj = 0; dj < 3; dj++)
                pv[j][dj] = *(const ull*)&Ps[buf][j][col + dj];

        #pragma unroll
        for (int di = 0; di < 3; di++) {
            ull w2[2][3];
            #pragma unroll
            for (int o2 = 0; o2 < 2; o2++)
                #pragma unroll
                for (int dj = 0; dj < 3; dj++)
                    w2[o2][dj] = *(const ull*)&wp[o2 * 9 + di * 3 + dj];
            #pragma unroll
            for (int k = 0; k < 4; k++)
                #pragma unroll
                for (int o2 = 0; o2 < 2; o2++)
                    #pragma unroll
                    for (int dj = 0; dj < 3; dj++)
                        fma2(acc[o2][k], w2[o2][dj], pv[k][dj]);
            if (di < 2) {
                #pragma unroll
                for (int j = 0; j < 3; j++)
                    #pragma unroll
                    for (int dj = 0; dj < 3; dj++)
                        pv[j][dj] = pv[j + 1][dj];
                #pragma unroll
                for (int dj = 0; dj < 3; dj++)
                    pv[3][dj] = *(const ull*)&Ps[buf][4 + di][col + dj];
            }
        }

        // ---- store prefetched channel into the other buffer ----
        if (more) {
            if (rhA <= 5) Ps[buf ^ 1][rhA][ccA].x = nA;
            if (rhA >= 4) Ps[buf ^ 1][rhA - 4][ccA].y = nA;
            if (isxB) {
                if (rhB <= 5) Ps[buf ^ 1][rhB][ccB].x = nB;
                if (rhB >= 4) Ps[buf ^ 1][rhB - 4][ccB].y = nB;
            } else if (iswB) ws2[buf ^ 1][wiB] = make_float2(nB, nB);
        }
        __syncthreads();
    }

    // ---- write partials ----
    float* rp = g_rotp + (size_t)(chunk * BB + b) * OC * HWP;
    #pragma unroll
    for (int o2 = 0; o2 < 2; o2++) {
        const int o = 2 * og + o2;
        #pragma unroll
        for (int k = 0; k < 4; k++) {
            float lo, hi; unpackf2(acc[o2][k], lo, hi);
            rp[(size_t)o * HWP + (h0 + k) * WW + w0 + col]     = lo;
            rp[(size_t)o * HWP + (h0 + 4 + k) * WW + w0 + col] = hi;
        }
    }
}

// ============================================================================
// Kernel 2: transpose x NCHW -> NHWC channel-paired float2 (for deform).
// ============================================================================
__global__ __launch_bounds__(256)
void transpose_kernel(const float* __restrict__ x)
{
    __shared__ float2 t[64][33];
    const int tid = threadIdx.x;
    const int tx = tid & 31, ty = tid >> 5;       // ty 0..7
    const int w0 = blockIdx.x * 32, h = blockIdx.y, b = blockIdx.z;

    const float* xb = x + ((size_t)b * CC) * HWP + h * WW + w0;
    #pragma unroll
    for (int k = 0; k < 8; k++) {
        int c = ty + 8 * k;                       // 0..63
        float v0 = xb[(size_t)c * HWP + tx];
        float v1 = xb[(size_t)(c + 64) * HWP + tx];
        t[c][tx] = make_float2(v0, v1);
    }
    __syncthreads();

    float2* ob = g_xt + ((size_t)(b * HH + h) * WW + w0) * 64;
    #pragma unroll
    for (int k = 0; k < 8; k++) {
        int cp = tx + 32 * (k & 1);
        int wl = ty + 8 * (k >> 1);
        ob[(size_t)wl * 64 + cp] = t[cp][wl];
    }
}

// ============================================================================
// Kernel 3: fused coef + deform gather, coalesced output.
// Block = 256 threads: cp(64) x pg(4). Tile = 1 row x 32 px x 128 ch.
// Each pg handles 8 pixels, processed as 4 independent pixel PAIRS (2x ILP).
// Thread cp handles channels cp and cp+64 (f32x2 paired) during compute.
// Results staged in padded smem planes, then written NCHW fully coalesced.
// ============================================================================
__global__ __launch_bounds__(256)
void deform_kernel(const float* __restrict__ wt, const float* __restrict__ rb,
                   float* __restrict__ out)
{
    __shared__ float2 wt2[16][64];
    __shared__ float4 cfs[9][32];
    __shared__ uint   ids[9][32];
    __shared__ float  resL[64][33];
    __shared__ float  resH[64][33];

    const int tid = threadIdx.x;
    const int cp = tid & 63;            // channel pair lane (warp-contiguous)
    const int pg = tid >> 6;            // pixel group 0..3 -> pixels 8pg..8pg+7
    const int w0 = blockIdx.x * 32;
    const int h  = blockIdx.y;
    const int b  = blockIdx.z;
    const int px0 = pg * 8;

    // stage channel-paired weight table
    for (int i = tid; i < 16 * 64; i += 256) {
        int s = i >> 6, c = i & 63;
        wt2[s][c] = make_float2(wt[c * 16 + s], wt[(c + 64) * 16 + s]);
    }

    // fused coef: items (t 0..8, p 0..31) = 288 ; sum CHUNKS partials + bias
    for (int i = tid; i < 288; i += 256) {
        int t = i >> 5, p = i & 31;
        int off = h * WW + w0 + p;
        int o0 = 2 * t, o1 = 2 * t + 1;
        // fc_bias start = (KS-(K-1)-1)/2 = 0.5
        float chv = rb[o0] + 0.5f + (float)(t / 3);
        float cwv = rb[o1] + 0.5f + (float)(t % 3);
        #pragma unroll
        for (int ch = 0; ch < CHUNKS; ch++) {
            const float* base = g_rotp + ((size_t)(ch * BB + b) * OC) * HWP + off;
            chv += base[(size_t)o0 * HWP];
            cwv += base[(size_t)o1 * HWP];
        }
        chv = fminf(fmaxf(chv, 0.0f), 3.0f);
        cwv = fminf(fmaxf(cwv, 0.0f), 3.0f);
        float h0f = floorf(chv), w0f = floorf(cwv);
        float lh = chv - h0f, lw = cwv - w0f;
        int h0i = (int)h0f, w0i = (int)w0f;
        int h1i = min(h0i + 1, 3), w1i = min(w0i + 1, 3);
        float4 cf;
        cf.x = (1.0f - lh) * (1.0f - lw);
        cf.y = (1.0f - lh) * lw;
        cf.z = lh * (1.0f - lw);
        cf.w = lh * lw;
        cfs[t][p] = cf;
        ids[t][p] = (uint)(h0i * 4 + w0i)
                  | ((uint)(h0i * 4 + w1i) << 8)
                  | ((uint)(h1i * 4 + w0i) << 16)
                  | ((uint)(h1i * 4 + w1i) << 24);
    }
    __syncthreads();

    const float2* xt = g_xt + (size_t)b * HWP * 64 + cp;
    const bool rok0 = (h >= 1), rok2 = (h <= HH - 2);

    // sliding window: 3 rows x 4 cols of channel-paired x values
    ull xv[3][4];
    #pragma unroll
    for (int dj = 0; dj < 2; dj++) {
        int gc = w0 + px0 - 1 + dj;
        bool cok = (unsigned)gc < (unsigned)WW;
        #pragma unroll
        for (int di = 0; di < 3; di++) {
            bool ok = cok && ((di == 0) ? rok0 : (di == 2) ? rok2 : true);
            ull v = 0ull;
            if (ok) v = *(const ull*)(xt + ((size_t)(h + di - 1) * WW + gc) * 64);
            xv[di][dj] = v;
        }
    }

    #pragma unroll
    for (int pp = 0; pp < 4; pp++) {
        const int p0 = px0 + 2 * pp;            // pixel A = p0, pixel B = p0+1
        // load 2 new columns (p0+1, p0+2 in global = w0+p0+1, w0+p0+2)
        #pragma unroll
        for (int dj = 2; dj < 4; dj++) {
            int gc = w0 + p0 - 1 + dj;
            bool cok = gc < WW;
            #pragma unroll
            for (int di = 0; di < 3; di++) {
                bool ok = cok && ((di == 0) ? rok0 : (di == 2) ? rok2 : true);
                ull v = 0ull;
                if (ok) v = *(const ull*)(xt + ((size_t)(h + di - 1) * WW + gc) * 64);
                xv[di][dj] = v;
            }
        }

        ull accA0 = 0ull, accA1 = 0ull, accB0 = 0ull, accB1 = 0ull;
        #pragma unroll
        for (int t = 0; t < 9; t++) {
            const int tr = t / 3, tc = t % 3;
            // ---- pixel A ----
            {
                const float4 cf = cfs[t][p0];
                const uint ox = ids[t][p0];
                ull g00 = *(const ull*)&wt2[ ox        & 15u][cp];
                ull g01 = *(const ull*)&wt2[(ox >> 8)  & 15u][cp];
                ull g10 = *(const ull*)&wt2[(ox >> 16) & 15u][cp];
                ull g11 = *(const ull*)&wt2[(ox >> 24) & 15u][cp];
                ull s0 = mul2(dupf2(cf.x), g00); fma2(s0, dupf2(cf.y), g01);
                ull s1 = mul2(dupf2(cf.z), g10); fma2(s1, dupf2(cf.w), g11);
                fma2(accA0, s0, xv[tr][tc]);
                fma2(accA1, s1, xv[tr][tc]);
            }
            // ---- pixel B ----
            {
                const float4 cf = cfs[t][p0 + 1];
                const uint ox = ids[t][p0 + 1];
                ull g00 = *(const ull*)&wt2[ ox        & 15u][cp];
                ull g01 = *(const ull*)&wt2[(ox >> 8)  & 15u][cp];
                ull g10 = *(const ull*)&wt2[(ox >> 16) & 15u][cp];
                ull g11 = *(const ull*)&wt2[(ox >> 24) & 15u][cp];
                ull s0 = mul2(dupf2(cf.x), g00); fma2(s0, dupf2(cf.y), g01);
                ull s1 = mul2(dupf2(cf.z), g10); fma2(s1, dupf2(cf.w), g11);
                fma2(accB0, s0, xv[tr][tc + 1]);
                fma2(accB1, s1, xv[tr][tc + 1]);
            }
        }

        float aL, aH, bL, bH;
        unpackf2(add2(accA0, accA1), aL, aH);
        unpackf2(add2(accB0, accB1), bL, bH);
        resL[cp][p0]     = aL; resH[cp][p0]     = aH;
        resL[cp][p0 + 1] = bL; resH[cp][p0 + 1] = bH;

        // shift window left by 2
        #pragma unroll
        for (int di = 0; di < 3; di++) { xv[di][0] = xv[di][2]; xv[di][1] = xv[di][3]; }
    }
    __syncthreads();

    // coalesced NCHW write: 128 ch x 32 px
    float* ob = out + (size_t)b * CC * HWP + h * WW + w0;
    #pragma unroll
    for (int i = tid; i < 128 * 32; i += 256) {
        int c = i >> 5, p = i & 31;
        float v = (c < 64) ? resL[c][p] : resH[c - 64][p];
        ob[(size_t)c * HWP + p] = v;
    }
}

// ============================================================================
extern "C" void kernel_launch(void* const* d_in, const int* in_sizes, int n_in,
                              void* d_out, int out_size)
{
    const float* x  = (const float*)d_in[0];   // [4,128,96,96]
    const float* rw = (const float*)d_in[1];   // [18,128,3,3]
    const float* rb = (const float*)d_in[2];   // [18]
    const float* wt = (const float*)d_in[3];   // [128,4,4]
    float* out = (float*)d_out;                // [4,128,96,96]

    conv_kernel<<<dim3(3, 12, BB * CHUNKS), 288>>>(x, rw);
    transpose_kernel<<<dim3(3, HH, BB), 256>>>(x);
    deform_kernel<<<dim3(3, HH, BB), 256>>>(wt, rb, out);
}

// round 4
// speedup vs baseline: 2.0778x; 1.0183x over previous
#include <cuda_runtime.h>
#include <cstdint>

typedef unsigned long long ull;
typedef unsigned int uint;

// Problem constants
#define BB   4
#define CC   128
#define HH   96
#define WW   96
#define OC   18          // G*K*K*2
#define HWP  (HH*WW)     // 9216
#define CHUNKS 2         // channel split for conv
#define CPC  (CC/CHUNKS) // 64 channels per chunk

// ---------------- scratch (static device arrays; no allocation) ----------------
__device__ float  g_rotp[CHUNKS * BB * OC * HWP];     // partial conv sums [chunk][b][o][h][w]
__device__ float2 g_xt[(size_t)BB * HWP * 64];        // NHWC channel-paired: [b][h][w][cp]=(x[cp],x[cp+64])

// ---------------- f32x2 helpers ----------------
__device__ __forceinline__ ull dupf2(float a) {
    ull r; asm("mov.b64 %0, {%1, %1};" : "=l"(r) : "f"(a)); return r;
}
__device__ __forceinline__ void unpackf2(ull v, float& a, float& b) {
    asm("mov.b64 {%0, %1}, %2;" : "=f"(a), "=f"(b) : "l"(v));
}
__device__ __forceinline__ void fma2(ull& d, ull a, ull b) {
    asm("fma.rn.f32x2 %0, %1, %2, %0;" : "+l"(d) : "l"(a), "l"(b));
}
__device__ __forceinline__ ull mul2(ull a, ull b) {
    ull r; asm("mul.rn.f32x2 %0, %1, %2;" : "=l"(r) : "l"(a), "l"(b)); return r;
}
__device__ __forceinline__ ull add2(ull a, ull b) {
    ull r; asm("add.rn.f32x2 %0, %1, %2;" : "=l"(r) : "l"(a), "l"(b)); return r;
}

// ============================================================================
// Fused kernel A: conv (blocks 0..287) + transpose (blocks 288..1439).
//
// CONV: rotation conv (18 out-ch, 128 in-ch, 3x3, pad 1), fp32 via f32x2.
//   Block = 288 threads: col(32) x og(9, 2 outputs each).
//   Tile = 8 pixel-rows x 32 cols (thread holds 4 vertical f32x2 row-pairs).
//   Channels split into 2 chunks of 64 (partial-sum buffers).
//   Weights staged once per 32-ch half; x staged 8 channels per barrier.
//   -> only 16 barriers total, no per-channel pipeline machinery.
//
// TRANSPOSE: x NCHW -> NHWC channel-paired float2 (for deform), overlapped
//   with conv in the same launch (conv leaves DRAM ~96% idle).
// ============================================================================
__global__ __launch_bounds__(288, 2)
void fusedA_kernel(const float* __restrict__ x, const float* __restrict__ rw)
{
    __shared__ union {
        struct {
            float  ws[32][OC * 9];    // weights for one 32-channel half, [c][o*9+t]
            float2 Ps[8][6][34];      // x tiles for 8 staged channels, row-paired
        } cv;
        float2 tr[64][33];            // transpose staging
    } sm;

    const int tid = threadIdx.x;
    const int bi  = blockIdx.x;

    if (bi >= 288) {
        // -------------------- TRANSPOSE role --------------------
        if (tid < 256) {
            const int ti = bi - 288;                 // 0..1151 = 3 x 96 x 4
            const int w0 = (ti % 3) * 32;
            const int h  = (ti / 3) % 96;
            const int b  = ti / 288;
            const int tx = tid & 31, ty = tid >> 5;  // ty 0..7

            const float* xb = x + ((size_t)b * CC) * HWP + h * WW + w0;
            #pragma unroll
            for (int k = 0; k < 8; k++) {
                int c = ty + 8 * k;                  // 0..63
                float v0 = xb[(size_t)c * HWP + tx];
                float v1 = xb[(size_t)(c + 64) * HWP + tx];
                sm.tr[c][tx] = make_float2(v0, v1);
            }
            __syncthreads();
            float2* ob = g_xt + ((size_t)(b * HH + h) * WW + w0) * 64;
            #pragma unroll
            for (int k = 0; k < 8; k++) {
                int cp = tx + 32 * (k & 1);
                int wl = ty + 8 * (k >> 1);
                ob[(size_t)wl * 64 + cp] = sm.tr[cp][wl];
            }
        } else {
            __syncthreads();   // keep barrier counts matched within block
        }
        return;
    }

    // -------------------- CONV role --------------------
    const int col = tid & 31;          // 0..31
    const int og  = tid >> 5;          // 0..8 -> outputs 2og, 2og+1

    const int w0 = (bi % 3) * 32;
    const int rest = bi / 3;
    const int h0 = (rest % 12) * 8;
    const int z  = rest / 12;          // 0..7
    const int b     = z >> 1;
    const int chunk = z & 1;
    const int cbase = chunk * CPC;

    ull acc[2][4];
    #pragma unroll
    for (int o2 = 0; o2 < 2; o2++)
        #pragma unroll
        for (int k = 0; k < 4; k++) acc[o2][k] = 0ull;

    const float* xb = x + ((size_t)(b * CC + cbase)) * HWP;

    for (int s = 0; s < 8; s++) {
        __syncthreads();
        // stage weights for a 32-channel half (at s==0 and s==4)
        if ((s & 3) == 0 && (s == 0 || s == 4)) {
            const int half = s >> 2;
            for (int i = tid; i < 32 * 162; i += 288) {
                int c = i / 162, r = i - c * 162;
                int o = r / 9, t9 = r - o * 9;
                sm.cv.ws[c][r] = rw[((size_t)o * CC + cbase + half * 32 + c) * 9 + t9];
            }
        }
        // stage x for 8 channels: items = 8 ch x (10 rows x 34 cols)
        {
            const float* xs = xb + (size_t)(s * 8) * HWP;
            for (int i = tid; i < 8 * 340; i += 288) {
                int ch = i / 340, pos = i - ch * 340;
                int rh = pos / 34, cc = pos - rh * 34;
                int gr = h0 - 1 + rh, gc = w0 - 1 + cc;
                float v = 0.0f;
                if ((unsigned)gr < (unsigned)HH && (unsigned)gc < (unsigned)WW)
                    v = xs[(size_t)ch * HWP + gr * WW + gc];
                if (rh <= 5) sm.cv.Ps[ch][rh][cc].x = v;       // row h0-1+rh
                if (rh >= 4) sm.cv.Ps[ch][rh - 4][cc].y = v;   // partner row +4
            }
        }
        __syncthreads();

        // compute 8 channels
        #pragma unroll 1
        for (int ci = 0; ci < 8; ci++) {
            const int cml = (s & 3) * 8 + ci;       // channel index within half
            const float* wrow = &sm.cv.ws[cml][og * 18];
            #pragma unroll
            for (int di = 0; di < 3; di++) {
                ull w2[2][3];
                #pragma unroll
                for (int o2 = 0; o2 < 2; o2++)
                    #pragma unroll
                    for (int dj = 0; dj < 3; dj++)
                        w2[o2][dj] = dupf2(wrow[o2 * 9 + di * 3 + dj]);
                #pragma unroll
                for (int k = 0; k < 4; k++) {
                    ull pv[3];
                    #pragma unroll
                    for (int dj = 0; dj < 3; dj++)
                        pv[dj] = *(const ull*)&sm.cv.Ps[ci][k + di][col + dj];
                    #pragma unroll
                    for (int o2 = 0; o2 < 2; o2++)
                        #pragma unroll
                        for (int dj = 0; dj < 3; dj++)
                            fma2(acc[o2][k], w2[o2][dj], pv[dj]);
                }
            }
        }
    }

    // write partials
    float* rp = g_rotp + (size_t)(chunk * BB + b) * OC * HWP;
    #pragma unroll
    for (int o2 = 0; o2 < 2; o2++) {
        const int o = 2 * og + o2;
        #pragma unroll
        for (int k = 0; k < 4; k++) {
            float lo, hi; unpackf2(acc[o2][k], lo, hi);
            rp[(size_t)o * HWP + (h0 + k) * WW + w0 + col]     = lo;
            rp[(size_t)o * HWP + (h0 + 4 + k) * WW + w0 + col] = hi;
        }
    }
}

// ============================================================================
// Kernel 2: fused coef + deform gather, coalesced output.
// Block = 256 threads: cp(64) x pg(4). Tile = 1 row x 32 px x 128 ch.
// Each pg handles 8 pixels, processed as 4 independent pixel PAIRS (2x ILP).
// Thread cp handles channels cp and cp+64 (f32x2 paired) during compute.
// Results staged in padded smem planes, then written NCHW fully coalesced.
// ============================================================================
__global__ __launch_bounds__(256)
void deform_kernel(const float* __restrict__ wt, const float* __restrict__ rb,
                   float* __restrict__ out)
{
    __shared__ float2 wt2[16][64];
    __shared__ float4 cfs[9][32];
    __shared__ uint   ids[9][32];
    __shared__ float  resL[64][33];
    __shared__ float  resH[64][33];

    const int tid = threadIdx.x;
    const int cp = tid & 63;            // channel pair lane (warp-contiguous)
    const int pg = tid >> 6;            // pixel group 0..3 -> pixels 8pg..8pg+7
    const int w0 = blockIdx.x * 32;
    const int h  = blockIdx.y;
    const int b  = blockIdx.z;
    const int px0 = pg * 8;

    // stage channel-paired weight table
    for (int i = tid; i < 16 * 64; i += 256) {
        int s = i >> 6, c = i & 63;
        wt2[s][c] = make_float2(wt[c * 16 + s], wt[(c + 64) * 16 + s]);
    }

    // fused coef: items (t 0..8, p 0..31) = 288 ; sum CHUNKS partials + bias
    for (int i = tid; i < 288; i += 256) {
        int t = i >> 5, p = i & 31;
        int off = h * WW + w0 + p;
        int o0 = 2 * t, o1 = 2 * t + 1;
        // fc_bias start = (KS-(K-1)-1)/2 = 0.5
        float chv = rb[o0] + 0.5f + (float)(t / 3);
        float cwv = rb[o1] + 0.5f + (float)(t % 3);
        #pragma unroll
        for (int ch = 0; ch < CHUNKS; ch++) {
            const float* base = g_rotp + ((size_t)(ch * BB + b) * OC) * HWP + off;
            chv += base[(size_t)o0 * HWP];
            cwv += base[(size_t)o1 * HWP];
        }
        chv = fminf(fmaxf(chv, 0.0f), 3.0f);
        cwv = fminf(fmaxf(cwv, 0.0f), 3.0f);
        float h0f = floorf(chv), w0f = floorf(cwv);
        float lh = chv - h0f, lw = cwv - w0f;
        int h0i = (int)h0f, w0i = (int)w0f;
        int h1i = min(h0i + 1, 3), w1i = min(w0i + 1, 3);
        float4 cf;
        cf.x = (1.0f - lh) * (1.0f - lw);
        cf.y = (1.0f - lh) * lw;
        cf.z = lh * (1.0f - lw);
        cf.w = lh * lw;
        cfs[t][p] = cf;
        ids[t][p] = (uint)(h0i * 4 + w0i)
                  | ((uint)(h0i * 4 + w1i) << 8)
                  | ((uint)(h1i * 4 + w0i) << 16)
                  | ((uint)(h1i * 4 + w1i) << 24);
    }
    __syncthreads();

    const float2* xt = g_xt + (size_t)b * HWP * 64 + cp;
    const bool rok0 = (h >= 1), rok2 = (h <= HH - 2);

    // sliding window: 3 rows x 4 cols of channel-paired x values
    ull xv[3][4];
    #pragma unroll
    for (int dj = 0; dj < 2; dj++) {
        int gc = w0 + px0 - 1 + dj;
        bool cok = (unsigned)gc < (unsigned)WW;
        #pragma unroll
        for (int di = 0; di < 3; di++) {
            bool ok = cok && ((di == 0) ? rok0 : (di == 2) ? rok2 : true);
            ull v = 0ull;
            if (ok) v = *(const ull*)(xt + ((size_t)(h + di - 1) * WW + gc) * 64);
            xv[di][dj] = v;
        }
    }

    #pragma unroll
    for (int pp = 0; pp < 4; pp++) {
        const int p0 = px0 + 2 * pp;            // pixel A = p0, pixel B = p0+1
        #pragma unroll
        for (int dj = 2; dj < 4; dj++) {
            int gc = w0 + p0 - 1 + dj;
            bool cok = gc < WW;
            #pragma unroll
            for (int di = 0; di < 3; di++) {
                bool ok = cok && ((di == 0) ? rok0 : (di == 2) ? rok2 : true);
                ull v = 0ull;
                if (ok) v = *(const ull*)(xt + ((size_t)(h + di - 1) * WW + gc) * 64);
                xv[di][dj] = v;
            }
        }

        ull accA0 = 0ull, accA1 = 0ull, accB0 = 0ull, accB1 = 0ull;
        #pragma unroll
        for (int t = 0; t < 9; t++) {
            const int tr = t / 3, tc = t % 3;
            { // pixel A
                const float4 cf = cfs[t][p0];
                const uint ox = ids[t][p0];
                ull g00 = *(const ull*)&wt2[ ox        & 15u][cp];
                ull g01 = *(const ull*)&wt2[(ox >> 8)  & 15u][cp];
                ull g10 = *(const ull*)&wt2[(ox >> 16) & 15u][cp];
                ull g11 = *(const ull*)&wt2[(ox >> 24) & 15u][cp];
                ull s0 = mul2(dupf2(cf.x), g00); fma2(s0, dupf2(cf.y), g01);
                ull s1 = mul2(dupf2(cf.z), g10); fma2(s1, dupf2(cf.w), g11);
                fma2(accA0, s0, xv[tr][tc]);
                fma2(accA1, s1, xv[tr][tc]);
            }
            { // pixel B
                const float4 cf = cfs[t][p0 + 1];
                const uint ox = ids[t][p0 + 1];
                ull g00 = *(const ull*)&wt2[ ox        & 15u][cp];
                ull g01 = *(const ull*)&wt2[(ox >> 8)  & 15u][cp];
                ull g10 = *(const ull*)&wt2[(ox >> 16) & 15u][cp];
                ull g11 = *(const ull*)&wt2[(ox >> 24) & 15u][cp];
                ull s0 = mul2(dupf2(cf.x), g00); fma2(s0, dupf2(cf.y), g01);
                ull s1 = mul2(dupf2(cf.z), g10); fma2(s1, dupf2(cf.w), g11);
                fma2(accB0, s0, xv[tr][tc + 1]);
                fma2(accB1, s1, xv[tr][tc + 1]);
            }
        }

        float aL, aH, bL, bH;
        unpackf2(add2(accA0, accA1), aL, aH);
        unpackf2(add2(accB0, accB1), bL, bH);
        resL[cp][p0]     = aL; resH[cp][p0]     = aH;
        resL[cp][p0 + 1] = bL; resH[cp][p0 + 1] = bH;

        #pragma unroll
        for (int di = 0; di < 3; di++) { xv[di][0] = xv[di][2]; xv[di][1] = xv[di][3]; }
    }
    __syncthreads();

    // coalesced NCHW write: 128 ch x 32 px
    float* ob = out + (size_t)b * CC * HWP + h * WW + w0;
    #pragma unroll
    for (int i = tid; i < 128 * 32; i += 256) {
        int c = i >> 5, p = i & 31;
        float v = (c < 64) ? resL[c][p] : resH[c - 64][p];
        ob[(size_t)c * HWP + p] = v;
    }
}

// ============================================================================
extern "C" void kernel_launch(void* const* d_in, const int* in_sizes, int n_in,
                              void* d_out, int out_size)
{
    const float* x  = (const float*)d_in[0];   // [4,128,96,96]
    const float* rw = (const float*)d_in[1];   // [18,128,3,3]
    const float* rb = (const float*)d_in[2];   // [18]
    const float* wt = (const float*)d_in[3];   // [128,4,4]
    float* out = (float*)d_out;                // [4,128,96,96]

    fusedA_kernel<<<1440, 288>>>(x, rw);
    deform_kernel<<<dim3(3, HH, BB), 256>>>(wt, rb, out);
}